// round 2
// baseline (speedup 1.0000x reference)
#include <cuda_runtime.h>
#include <stdint.h>

// ---------------------------------------------------------------------------
// HashEncoder (Instant-NGP multires hash grid): B=2097152 pts, D=3, L=16, C=2
// base_res=16, desired=2048, log2_hashmap=19.
//
// Level table (verified: offsets sum to TOTAL_PARAMS = 6098120):
//   res : 16 23 31 43 59 | 81 112 154 213 295 407 562 777 1073 1483 2048
//   l<5 dense (res^3, aligned to 8), l>=5 hashed with hmap = 2^19.
// ---------------------------------------------------------------------------

#define NLEV 16
#define BLOCK 256
#define PTS_PER_BLK 32   // 8 threads per point

__constant__ uint32_t c_res[NLEV] = {
    16u, 23u, 31u, 43u, 59u, 81u, 112u, 154u,
    213u, 295u, 407u, 562u, 777u, 1073u, 1483u, 2048u
};
__constant__ uint32_t c_off[NLEV] = {
    0u, 4096u, 16264u, 46056u, 125568u, 330952u, 855240u, 1379528u,
    1903816u, 2428104u, 2952392u, 3476680u, 4000968u, 4525256u, 5049544u, 5573832u
};

// Per-level scale in fp32, computed in double on device to match numpy's
//   exp2(l * (log2(128)/15)) * 16 - 1   (log2(128)=7 exactly).
__device__ float g_scales[NLEV];

__global__ void scales_init_kernel() {
    int l = threadIdx.x;
    if (l < NLEV) {
        double s = exp2((double)l * (7.0 / 15.0)) * 16.0 - 1.0;
        g_scales[l] = (float)s;
    }
}

__global__ __launch_bounds__(BLOCK)
void hash_encode_kernel(const float* __restrict__ inputs,
                        const float2* __restrict__ emb,
                        float4* __restrict__ out,
                        int npts)
{
    __shared__ float s_in[PTS_PER_BLK * 3];
    __shared__ float s_scale[NLEV];

    const int tid = threadIdx.x;

    // Stage this block's 32 points (96 floats) coalesced into smem.
    {
        int gidx = blockIdx.x * (PTS_PER_BLK * 3) + tid;
        if (tid < PTS_PER_BLK * 3 && gidx < npts * 3)
            s_in[tid] = inputs[gidx];
        if (tid < NLEV)
            s_scale[tid] = g_scales[tid];
    }
    __syncthreads();

    const int p = tid >> 3;       // point within block (0..31)
    const int s = tid & 7;        // sub-thread: handles levels 2s, 2s+1
    const long long point = (long long)blockIdx.x * PTS_PER_BLK + p;
    if (point >= npts) return;

    const float x = s_in[p * 3 + 0];
    const float y = s_in[p * 3 + 1];
    const float z = s_in[p * 3 + 2];

    float4 r;

    #pragma unroll
    for (int i = 0; i < 2; ++i) {
        const int l = (s << 1) + i;
        const float scale  = s_scale[l];
        const uint32_t res = c_res[l];
        const uint32_t off = c_off[l];

        // pos = x*scale + 0.5 with NO fma contraction (must match reference
        // rounding so floor() picks the same grid cell).
        const float posx = __fadd_rn(__fmul_rn(x, scale), 0.5f);
        const float posy = __fadd_rn(__fmul_rn(y, scale), 0.5f);
        const float posz = __fadd_rn(__fmul_rn(z, scale), 0.5f);
        const float fx = floorf(posx), fy = floorf(posy), fz = floorf(posz);
        const float tx = posx - fx,  ty = posy - fy,  tz = posz - fz;
        const uint32_t gx = (uint32_t)fx, gy = (uint32_t)fy, gz = (uint32_t)fz;
        const uint32_t rm1 = res - 1u;
        const uint32_t x0 = min(gx,      rm1), x1 = min(gx + 1u, rm1);
        const uint32_t y0 = min(gy,      rm1), y1 = min(gy + 1u, rm1);
        const uint32_t z0 = min(gz,      rm1), z1 = min(gz + 1u, rm1);

        // Corner order: bit0->x, bit1->y, bit2->z (matches reference).
        uint32_t idx[8];
        if (l >= 5) {
            // hashed level: hmap = 2^19 for all hash levels -> mask
            const uint32_t hy0 = y0 * 2654435761u, hy1 = y1 * 2654435761u;
            const uint32_t hz0 = z0 * 805459861u,  hz1 = z1 * 805459861u;
            idx[0] = (x0 ^ hy0 ^ hz0) & 0x7FFFFu;
            idx[1] = (x1 ^ hy0 ^ hz0) & 0x7FFFFu;
            idx[2] = (x0 ^ hy1 ^ hz0) & 0x7FFFFu;
            idx[3] = (x1 ^ hy1 ^ hz0) & 0x7FFFFu;
            idx[4] = (x0 ^ hy0 ^ hz1) & 0x7FFFFu;
            idx[5] = (x1 ^ hy0 ^ hz1) & 0x7FFFFu;
            idx[6] = (x0 ^ hy1 ^ hz1) & 0x7FFFFu;
            idx[7] = (x1 ^ hy1 ^ hz1) & 0x7FFFFu;
        } else {
            const uint32_t r2  = res * res;
            const uint32_t by0 = y0 * res, by1 = y1 * res;
            const uint32_t bz0 = z0 * r2,  bz1 = z1 * r2;
            idx[0] = x0 + by0 + bz0;  idx[1] = x1 + by0 + bz0;
            idx[2] = x0 + by1 + bz0;  idx[3] = x1 + by1 + bz0;
            idx[4] = x0 + by0 + bz1;  idx[5] = x1 + by0 + bz1;
            idx[6] = x0 + by1 + bz1;  idx[7] = x1 + by1 + bz1;
        }

        // Batched gathers: all 8 issued before any consumer -> MLP=8.
        float2 e[8];
        #pragma unroll
        for (int c = 0; c < 8; ++c)
            e[c] = __ldg(emb + off + idx[c]);

        const float wx0 = 1.0f - tx, wy0 = 1.0f - ty, wz0 = 1.0f - tz;
        float a0 = 0.0f, a1 = 0.0f;
        #pragma unroll
        for (int c = 0; c < 8; ++c) {
            const float wx = (c & 1) ? tx : wx0;
            const float wy = (c & 2) ? ty : wy0;
            const float wz = (c & 4) ? tz : wz0;
            const float w  = __fmul_rn(__fmul_rn(wx, wy), wz);
            a0 = fmaf(w, e[c].x, a0);
            a1 = fmaf(w, e[c].y, a1);
        }
        if (i == 0) { r.x = a0; r.y = a1; }
        else        { r.z = a0; r.w = a1; }
    }

    // out[point, 32 floats] = 8 float4; thread s writes float4 #s.
    // Warp = 4 points x 8 subthreads -> 512B contiguous, fully coalesced.
    out[point * 8 + s] = r;
}

extern "C" void kernel_launch(void* const* d_in, const int* in_sizes, int n_in,
                              void* d_out, int out_size)
{
    const float*  inputs = (const float*)d_in[0];
    const float2* emb    = (const float2*)d_in[1];
    float4*       out    = (float4*)d_out;

    const int npts = in_sizes[0] / 3;

    scales_init_kernel<<<1, NLEV>>>();

    const int total_threads = npts * 8;
    const int nblocks = (total_threads + BLOCK - 1) / BLOCK;
    hash_encode_kernel<<<nblocks, BLOCK>>>(inputs, emb, out, npts);
}

// round 4
// speedup vs baseline: 1.0567x; 1.0567x over previous
#include <cuda_runtime.h>
#include <stdint.h>

// ---------------------------------------------------------------------------
// HashEncoder (Instant-NGP multires hash grid): B=2097152 pts, D=3, L=16, C=2
// base_res=16, desired=2048, log2_hashmap=19.
//
// Level table (offsets sum to TOTAL_PARAMS = 6098120):
//   res : 16 23 31 43 59 | 81 112 154 213 295 407 562 777 1073 1483 2048
//   l<5 dense (res^3 aligned to 8), l>=5 hashed with hmap = 2^19.
//
// R3/R4: corner-pair gathers. The 8 corners form 4 x-pairs; whenever
// idx1 == idx0^1 (~50% of pairs) both corners live in one aligned float4
// -> one LDG.128 instead of two LDG.64 -> ~25% fewer L1tex wavefronts
// (L1tex is the measured binder: 93.7% in R2).
// ---------------------------------------------------------------------------

#define NLEV 16
#define BLOCK 256
#define PTS_PER_BLK 32   // 8 threads per point, 2 levels per thread

__constant__ uint32_t c_res[NLEV] = {
    16u, 23u, 31u, 43u, 59u, 81u, 112u, 154u,
    213u, 295u, 407u, 562u, 777u, 1073u, 1483u, 2048u
};
__constant__ uint32_t c_off[NLEV] = {
    0u, 4096u, 16264u, 46056u, 125568u, 330952u, 855240u, 1379528u,
    1903816u, 2428104u, 2952392u, 3476680u, 4000968u, 4525256u, 5049544u, 5573832u
};

__device__ float g_scales[NLEV];

__global__ void scales_init_kernel() {
    int l = threadIdx.x;
    if (l < NLEV) {
        double s = exp2((double)l * (7.0 / 15.0)) * 16.0 - 1.0;
        g_scales[l] = (float)s;
    }
}

// Predicated pair-gather: if pr, one aligned ld.global.nc.v4 fetches both
// corners; else two ld.global.nc.v2. The untaken path issues NO load (true
// predication, no divergence machinery). Outputs are pre-zeroed so neither
// path ever reads formally-undefined registers.
__device__ __forceinline__ void pair_gather(const float2* __restrict__ tab,
                                            uint32_t a, uint32_t b,
                                            float2& ea, float2& eb)
{
    const unsigned pr = (b == (a ^ 1u)) ? 1u : 0u;
    const float2* pa = tab + a;
    const float2* pb = tab + b;
    const float4* p4 = (const float4*)(tab + (a & ~1u));
    float x0, x1, x2, x3, u0, u1, u2, u3;
    asm volatile(
        "{\n\t"
        ".reg .pred p;\n\t"
        "setp.ne.u32 p, %8, 0;\n\t"
        "mov.f32 %0, 0f00000000;\n\t"
        "mov.f32 %1, 0f00000000;\n\t"
        "mov.f32 %2, 0f00000000;\n\t"
        "mov.f32 %3, 0f00000000;\n\t"
        "mov.f32 %4, 0f00000000;\n\t"
        "mov.f32 %5, 0f00000000;\n\t"
        "mov.f32 %6, 0f00000000;\n\t"
        "mov.f32 %7, 0f00000000;\n\t"
        "@p  ld.global.nc.v4.f32 {%0,%1,%2,%3}, [%9];\n\t"
        "@!p ld.global.nc.v2.f32 {%4,%5}, [%10];\n\t"
        "@!p ld.global.nc.v2.f32 {%6,%7}, [%11];\n\t"
        "}"
        : "=f"(x0), "=f"(x1), "=f"(x2), "=f"(x3),
          "=f"(u0), "=f"(u1), "=f"(u2), "=f"(u3)
        : "r"(pr), "l"(p4), "l"(pa), "l"(pb));
    if (pr) {
        const bool odd = (a & 1u) != 0u;
        ea.x = odd ? x2 : x0;  ea.y = odd ? x3 : x1;
        eb.x = odd ? x0 : x2;  eb.y = odd ? x1 : x3;
    } else {
        ea.x = u0; ea.y = u1;
        eb.x = u2; eb.y = u3;
    }
}

__global__ __launch_bounds__(BLOCK)
void hash_encode_kernel(const float* __restrict__ inputs,
                        const float2* __restrict__ emb,
                        float4* __restrict__ out,
                        int npts)
{
    __shared__ float s_in[PTS_PER_BLK * 3];
    __shared__ float s_scale[NLEV];

    const int tid = threadIdx.x;
    {
        int gidx = blockIdx.x * (PTS_PER_BLK * 3) + tid;
        if (tid < PTS_PER_BLK * 3 && gidx < npts * 3)
            s_in[tid] = inputs[gidx];
        if (tid < NLEV)
            s_scale[tid] = g_scales[tid];
    }
    __syncthreads();

    const int p = tid >> 3;       // point within block (0..31)
    const int s = tid & 7;        // sub-thread: handles levels 2s, 2s+1
    const long long point = (long long)blockIdx.x * PTS_PER_BLK + p;
    if (point >= npts) return;

    const float x = s_in[p * 3 + 0];
    const float y = s_in[p * 3 + 1];
    const float z = s_in[p * 3 + 2];

    float4 r;

    #pragma unroll
    for (int i = 0; i < 2; ++i) {
        const int l = (s << 1) + i;
        const float scale  = s_scale[l];
        const uint32_t res = c_res[l];
        const float2* __restrict__ tab = emb + c_off[l];

        // pos = x*scale + 0.5, NO fma contraction (floor must match reference).
        const float posx = __fadd_rn(__fmul_rn(x, scale), 0.5f);
        const float posy = __fadd_rn(__fmul_rn(y, scale), 0.5f);
        const float posz = __fadd_rn(__fmul_rn(z, scale), 0.5f);
        const float fx = floorf(posx), fy = floorf(posy), fz = floorf(posz);
        const float tx = posx - fx,  ty = posy - fy,  tz = posz - fz;
        const uint32_t gx = (uint32_t)fx, gy = (uint32_t)fy, gz = (uint32_t)fz;
        const uint32_t rm1 = res - 1u;
        const uint32_t x0 = min(gx,      rm1), x1 = min(gx + 1u, rm1);
        const uint32_t y0 = min(gy,      rm1), y1 = min(gy + 1u, rm1);
        const uint32_t z0 = min(gz,      rm1), z1 = min(gz + 1u, rm1);

        // 4 x-pairs; pair q has (y,z) bits (q&1, q>>1).
        uint32_t ia[4], ib[4];
        if (l >= 5) {
            const uint32_t hy0 = y0 * 2654435761u, hy1 = y1 * 2654435761u;
            const uint32_t hz0 = z0 * 805459861u,  hz1 = z1 * 805459861u;
            const uint32_t m = 0x7FFFFu;
            ia[0] = (x0 ^ hy0 ^ hz0) & m;  ib[0] = (x1 ^ hy0 ^ hz0) & m;
            ia[1] = (x0 ^ hy1 ^ hz0) & m;  ib[1] = (x1 ^ hy1 ^ hz0) & m;
            ia[2] = (x0 ^ hy0 ^ hz1) & m;  ib[2] = (x1 ^ hy0 ^ hz1) & m;
            ia[3] = (x0 ^ hy1 ^ hz1) & m;  ib[3] = (x1 ^ hy1 ^ hz1) & m;
        } else {
            const uint32_t r2  = res * res;
            const uint32_t by0 = y0 * res, by1 = y1 * res;
            const uint32_t bz0 = z0 * r2,  bz1 = z1 * r2;
            ia[0] = x0 + by0 + bz0;  ib[0] = x1 + by0 + bz0;
            ia[1] = x0 + by1 + bz0;  ib[1] = x1 + by1 + bz0;
            ia[2] = x0 + by0 + bz1;  ib[2] = x1 + by0 + bz1;
            ia[3] = x0 + by1 + bz1;  ib[3] = x1 + by1 + bz1;
        }

        float2 ea[4], eb[4];
        #pragma unroll
        for (int q = 0; q < 4; ++q)
            pair_gather(tab, ia[q], ib[q], ea[q], eb[q]);

        const float wx0 = 1.0f - tx, wy0 = 1.0f - ty, wz0 = 1.0f - tz;
        float a0 = 0.0f, a1 = 0.0f;
        #pragma unroll
        for (int q = 0; q < 4; ++q) {
            const float wy = (q & 1) ? ty : wy0;
            const float wz = (q & 2) ? tz : wz0;
            const float wyz = __fmul_rn(wy, wz);
            const float wa  = __fmul_rn(wx0, wyz);
            const float wb  = __fmul_rn(tx,  wyz);
            a0 = fmaf(wa, ea[q].x, a0);
            a1 = fmaf(wa, ea[q].y, a1);
            a0 = fmaf(wb, eb[q].x, a0);
            a1 = fmaf(wb, eb[q].y, a1);
        }
        if (i == 0) { r.x = a0; r.y = a1; }
        else        { r.z = a0; r.w = a1; }
    }

    // Warp = 4 points x 8 subthreads -> 512B contiguous store, fully coalesced.
    out[point * 8 + s] = r;
}

extern "C" void kernel_launch(void* const* d_in, const int* in_sizes, int n_in,
                              void* d_out, int out_size)
{
    const float*  inputs = (const float*)d_in[0];
    const float2* emb    = (const float2*)d_in[1];
    float4*       out    = (float4*)d_out;

    const int npts = in_sizes[0] / 3;

    scales_init_kernel<<<1, NLEV>>>();

    const int total_threads = npts * 8;
    const int nblocks = (total_threads + BLOCK - 1) / BLOCK;
    hash_encode_kernel<<<nblocks, BLOCK>>>(inputs, emb, out, npts);
}

// round 7
// speedup vs baseline: 1.1023x; 1.0431x over previous
#include <cuda_runtime.h>
#include <cuda_fp16.h>
#include <stdint.h>

// ---------------------------------------------------------------------------
// HashEncoder (Instant-NGP multires hash grid): B=2097152 pts, D=3, L=16, C=2
// base_res=16, desired=2048, log2_hashmap=19.
//
// Level table (offsets sum to TOTAL_PARAMS = 6098120):
//   res : 16 23 31 43 59 | 81 112 154 213 295 407 562 777 1073 1483 2048
//   l<5 dense (res^3 aligned to 8), l>=5 hashed with hmap = 2^19.
//
// R5: fp16 pair shadow table. Measured R4: scattered LDG.128 costs ~2 wf/lane
// (8B return per lane per wavefront), so f32 pairing was wavefront-neutral.
// Fix: fp16x2 shadow table -> a paired corner duo (idx1==idx0^1, ~50%) is ONE
// aligned 8-byte load = 1 wavefront for 2 corners. Unpaired corners stay f32.
// Expected -25% L1tex work (the binder at ~95%).
// ---------------------------------------------------------------------------

#define NLEV 16
#define BLOCK 256
#define PTS_PER_BLK 32            // 8 threads per point, 2 levels per thread
#define TOTAL_PARAMS 6098120

__constant__ uint32_t c_res[NLEV] = {
    16u, 23u, 31u, 43u, 59u, 81u, 112u, 154u,
    213u, 295u, 407u, 562u, 777u, 1073u, 1483u, 2048u
};
__constant__ uint32_t c_off[NLEV] = {
    0u, 4096u, 16264u, 46056u, 125568u, 330952u, 855240u, 1379528u,
    1903816u, 2428104u, 2952392u, 3476680u, 4000968u, 4525256u, 5049544u, 5573832u
};

__device__ float g_scales[NLEV];
// fp16x2 shadow of the embedding table (one uint32 per entry), 24.4 MB static.
__device__ __align__(128) uint32_t g_half[TOTAL_PARAMS];

__global__ void scales_init_kernel() {
    int l = threadIdx.x;
    if (l < NLEV) {
        double s = exp2((double)l * (7.0 / 15.0)) * 16.0 - 1.0;
        g_scales[l] = (float)s;
    }
}

// Convert f32 table -> fp16x2 shadow. Each thread: 2 entries (16B load, 8B store).
__global__ __launch_bounds__(256)
void convert_kernel(const float4* __restrict__ emb4) {
    int i = blockIdx.x * blockDim.x + threadIdx.x;   // pair index
    if (i < TOTAL_PARAMS / 2) {
        float4 e = emb4[i];                          // entries 2i, 2i+1
        __half2 h0 = __floats2half2_rn(e.x, e.y);
        __half2 h1 = __floats2half2_rn(e.z, e.w);
        uint32_t w0 = *(uint32_t*)&h0;
        uint32_t w1 = *(uint32_t*)&h1;
        *(uint64_t*)&g_half[2 * i] = ((uint64_t)w1 << 32) | w0;
    }
}

// Hybrid pair-gather: if pr (b == a^1), ONE 8-byte fp16 load fetches both
// corners (1 wavefront); else two f32 ld.global.nc.v2. True predication,
// no divergence machinery. Outputs pre-zeroed (no undefined reads).
__device__ __forceinline__ void pair_gather(const float2* __restrict__ tabf,
                                            const uint32_t* __restrict__ tabh,
                                            uint32_t a, uint32_t b,
                                            float2& ea, float2& eb)
{
    const unsigned pr = (b == (a ^ 1u)) ? 1u : 0u;
    const float2*   pa = tabf + a;
    const float2*   pb = tabf + b;
    const uint32_t* ph = tabh + (a & ~1u);   // 8B-aligned (offsets all even)
    unsigned long long hp;
    float a0, a1, b0, b1;
    asm volatile(
        "{\n\t"
        ".reg .pred p;\n\t"
        "setp.ne.u32 p, %5, 0;\n\t"
        "mov.u64 %0, 0;\n\t"
        "mov.f32 %1, 0f00000000;\n\t"
        "mov.f32 %2, 0f00000000;\n\t"
        "mov.f32 %3, 0f00000000;\n\t"
        "mov.f32 %4, 0f00000000;\n\t"
        "@p  ld.global.nc.u64 %0, [%6];\n\t"
        "@!p ld.global.nc.v2.f32 {%1,%2}, [%7];\n\t"
        "@!p ld.global.nc.v2.f32 {%3,%4}, [%8];\n\t"
        "}"
        : "=l"(hp), "=f"(a0), "=f"(a1), "=f"(b0), "=f"(b1)
        : "r"(pr), "l"(ph), "l"(pa), "l"(pb));
    if (pr) {
        const uint32_t w0 = (uint32_t)hp;          // entry a&~1
        const uint32_t w1 = (uint32_t)(hp >> 32);  // entry a|1
        const float2 e0 = __half22float2(*(const __half2*)&w0);
        const float2 e1 = __half22float2(*(const __half2*)&w1);
        const bool odd = (a & 1u) != 0u;
        ea = odd ? e1 : e0;
        eb = odd ? e0 : e1;
    } else {
        ea = make_float2(a0, a1);
        eb = make_float2(b0, b1);
    }
}

__global__ __launch_bounds__(BLOCK)
void hash_encode_kernel(const float* __restrict__ inputs,
                        const float2* __restrict__ emb,
                        float4* __restrict__ out,
                        int npts)
{
    __shared__ float s_in[PTS_PER_BLK * 3];
    __shared__ float s_scale[NLEV];

    const int tid = threadIdx.x;
    {
        int gidx = blockIdx.x * (PTS_PER_BLK * 3) + tid;
        if (tid < PTS_PER_BLK * 3 && gidx < npts * 3)
            s_in[tid] = inputs[gidx];
        if (tid < NLEV)
            s_scale[tid] = g_scales[tid];
    }
    __syncthreads();

    const int p = tid >> 3;       // point within block (0..31)
    const int s = tid & 7;        // sub-thread: handles levels 2s, 2s+1
    const long long point = (long long)blockIdx.x * PTS_PER_BLK + p;
    if (point >= npts) return;

    const float x = s_in[p * 3 + 0];
    const float y = s_in[p * 3 + 1];
    const float z = s_in[p * 3 + 2];

    float4 r;

    #pragma unroll
    for (int i = 0; i < 2; ++i) {
        const int l = (s << 1) + i;
        const float scale  = s_scale[l];
        const uint32_t res = c_res[l];
        const float2*   __restrict__ tabf = emb    + c_off[l];
        const uint32_t* __restrict__ tabh = g_half + c_off[l];

        // pos = x*scale + 0.5, NO fma contraction (floor must match reference).
        const float posx = __fadd_rn(__fmul_rn(x, scale), 0.5f);
        const float posy = __fadd_rn(__fmul_rn(y, scale), 0.5f);
        const float posz = __fadd_rn(__fmul_rn(z, scale), 0.5f);
        const float fx = floorf(posx), fy = floorf(posy), fz = floorf(posz);
        const float tx = posx - fx,  ty = posy - fy,  tz = posz - fz;
        const uint32_t gx = (uint32_t)fx, gy = (uint32_t)fy, gz = (uint32_t)fz;
        const uint32_t rm1 = res - 1u;
        const uint32_t x0 = min(gx,      rm1), x1 = min(gx + 1u, rm1);
        const uint32_t y0 = min(gy,      rm1), y1 = min(gy + 1u, rm1);
        const uint32_t z0 = min(gz,      rm1), z1 = min(gz + 1u, rm1);

        // 4 x-pairs; pair q has (y,z) bits (q&1, q>>1).
        uint32_t ia[4], ib[4];
        if (l >= 5) {
            const uint32_t hy0 = y0 * 2654435761u, hy1 = y1 * 2654435761u;
            const uint32_t hz0 = z0 * 805459861u,  hz1 = z1 * 805459861u;
            const uint32_t m = 0x7FFFFu;
            ia[0] = (x0 ^ hy0 ^ hz0) & m;  ib[0] = (x1 ^ hy0 ^ hz0) & m;
            ia[1] = (x0 ^ hy1 ^ hz0) & m;  ib[1] = (x1 ^ hy1 ^ hz0) & m;
            ia[2] = (x0 ^ hy0 ^ hz1) & m;  ib[2] = (x1 ^ hy0 ^ hz1) & m;
            ia[3] = (x0 ^ hy1 ^ hz1) & m;  ib[3] = (x1 ^ hy1 ^ hz1) & m;
        } else {
            const uint32_t r2  = res * res;
            const uint32_t by0 = y0 * res, by1 = y1 * res;
            const uint32_t bz0 = z0 * r2,  bz1 = z1 * r2;
            ia[0] = x0 + by0 + bz0;  ib[0] = x1 + by0 + bz0;
            ia[1] = x0 + by1 + bz0;  ib[1] = x1 + by1 + bz0;
            ia[2] = x0 + by0 + bz1;  ib[2] = x1 + by0 + bz1;
            ia[3] = x0 + by1 + bz1;  ib[3] = x1 + by1 + bz1;
        }

        float2 ea[4], eb[4];
        #pragma unroll
        for (int q = 0; q < 4; ++q)
            pair_gather(tabf, tabh, ia[q], ib[q], ea[q], eb[q]);

        const float wx0 = 1.0f - tx, wy0 = 1.0f - ty, wz0 = 1.0f - tz;
        float a0 = 0.0f, a1 = 0.0f;
        #pragma unroll
        for (int q = 0; q < 4; ++q) {
            const float wy = (q & 1) ? ty : wy0;
            const float wz = (q & 2) ? tz : wz0;
            const float wyz = __fmul_rn(wy, wz);
            const float wa  = __fmul_rn(wx0, wyz);
            const float wb  = __fmul_rn(tx,  wyz);
            a0 = fmaf(wa, ea[q].x, a0);
            a1 = fmaf(wa, ea[q].y, a1);
            a0 = fmaf(wb, eb[q].x, a0);
            a1 = fmaf(wb, eb[q].y, a1);
        }
        if (i == 0) { r.x = a0; r.y = a1; }
        else        { r.z = a0; r.w = a1; }
    }

    // Warp = 4 points x 8 subthreads -> 512B contiguous store, fully coalesced.
    out[point * 8 + s] = r;
}

extern "C" void kernel_launch(void* const* d_in, const int* in_sizes, int n_in,
                              void* d_out, int out_size)
{
    const float*  inputs = (const float*)d_in[0];
    const float2* emb    = (const float2*)d_in[1];
    float4*       out    = (float4*)d_out;

    const int npts = in_sizes[0] / 3;

    scales_init_kernel<<<1, NLEV>>>();

    const int npairs = TOTAL_PARAMS / 2;
    convert_kernel<<<(npairs + 255) / 256, 256>>>((const float4*)emb);

    const int total_threads = npts * 8;
    const int nblocks = (total_threads + BLOCK - 1) / BLOCK;
    hash_encode_kernel<<<nblocks, BLOCK>>>(inputs, emb, out, npts);
}